// round 1
// baseline (speedup 1.0000x reference)
#include <cuda_runtime.h>
#include <cstdint>

#define MASK_ID 50264
#define Bb 16
#define Ss 2048
#define Hh 1024
#define Ll 128
#define Mm (Bb*Ll)   // 2048

// ---------------- device scratch (static allocation only) ----------------
__device__ int   g_maskpos[Bb];
__device__ int   g_off[Ll];
__device__ float g_x[Bb*Hh];
__device__ float g_xn[Bb];
__device__ float g_y[(size_t)Mm*Hh];     // 8 MB projected ys
__device__ float g_elab[Mm];
__device__ float g_eev[Mm];

// ---------------- kernel 1: dtype detect + mask_pos + offsets ----------------
__global__ void prep_kernel(const int* __restrict__ ids_w, const int* __restrict__ off_w) {
    __shared__ int s_flag;
    __shared__ int s_min[256];
    int t = threadIdx.x;
    if (t == 0) s_flag = 0;
    __syncthreads();
    // If data is int64 (values < 2^31), every odd 32-bit word is 0.
    int nz = 0;
    for (int i = 1 + 2 * t; i < 2048; i += 512) nz |= ids_w[i];
    if (nz) atomicOr(&s_flag, 1);
    __syncthreads();
    const bool is64 = (s_flag == 0);

    if (t < Ll) {
        g_off[t] = is64 ? (int)((const long long*)off_w)[t] : off_w[t];
    }
    const long long* ids64 = (const long long*)ids_w;
    for (int b = 0; b < Bb; b++) {
        int mi = 0x7fffffff;
        for (int s = t; s < Ss; s += 256) {
            long long v = is64 ? ids64[(size_t)b * Ss + s] : (long long)ids_w[b * Ss + s];
            if (v == MASK_ID && s < mi) mi = s;
        }
        s_min[t] = mi;
        __syncthreads();
        for (int w = 128; w > 0; w >>= 1) {
            if (t < w) s_min[t] = min(s_min[t], s_min[t + w]);
            __syncthreads();
        }
        if (t == 0) g_maskpos[b] = (s_min[0] == 0x7fffffff) ? 0 : s_min[0];
        __syncthreads();
    }
}

// ---------------- kernel 2: project x rows (16 x 1024) + norms ----------------
__global__ void xproj_kernel(const float* __restrict__ q, const float* __restrict__ Wm,
                             const float* __restrict__ bias) {
    __shared__ float v[Hh];
    __shared__ float ssq[8];
    int b = blockIdx.x, t = threadIdx.x;
    int mp = g_maskpos[b];
    const float4* src = (const float4*)(q + ((size_t)b * Ss + mp) * Hh);
    ((float4*)v)[t] = src[t];               // 256 threads * 16B = 4KB
    __syncthreads();
    int w = t >> 5, lane = t & 31;
    float sq = 0.f;
    for (int oi = 0; oi < Hh / 8; oi++) {   // 128 outputs per warp
        int o = w * (Hh / 8) + oi;
        const float* wr = Wm + (size_t)o * Hh;
        float s = 0.f;
        for (int h = lane * 4; h < Hh; h += 128) {
            float4 wv = *(const float4*)(wr + h);
            float4 vv = *(const float4*)(v + h);
            s += wv.x * vv.x + wv.y * vv.y + wv.z * vv.z + wv.w * vv.w;
        }
        #pragma unroll
        for (int d = 16; d > 0; d >>= 1) s += __shfl_xor_sync(0xffffffffu, s, d);
        if (lane == 0) {
            s += bias[o];
            g_x[b * Hh + o] = s;
            sq += s * s;
        }
    }
    if (lane == 0) ssq[w] = sq;
    __syncthreads();
    if (t == 0) {
        float tot = 0.f;
        #pragma unroll
        for (int i = 0; i < 8; i++) tot += ssq[i];
        g_xn[b] = sqrtf(tot);
    }
}

// ---------------- kernel 3: gathered SGEMM  Y[r,n] = sum_k A[r,k]*W[n,k] + b[n] ----------------
#define BM 64
#define BN 64
#define BK 16

__device__ __forceinline__ unsigned long long dup_f32(float a) {
    unsigned long long r;
    asm("mov.b64 %0, {%1, %1};" : "=l"(r) : "r"(__float_as_uint(a)));
    return r;
}

__global__ __launch_bounds__(256) void gemm_kernel(const float* __restrict__ seq,
                                                   const float* __restrict__ Wm,
                                                   const float* __restrict__ bias) {
    __shared__ float As[BK][BM];
    __shared__ float Bs[BK][BN];
    int t = threadIdx.x;
    int tx = t & 15, ty = t >> 4;
    int m0 = blockIdx.y * BM, n0 = blockIdx.x * BN;

    // loader assignment: li = row within tile, lk = starting k (4 consecutive)
    int li = t >> 2;
    int lk = (t & 3) * 4;
    int r = m0 + li;
    int bb = r >> 7, ll = r & 127;
    const float* arow = seq + ((size_t)bb * Ss + g_off[ll]) * Hh;
    const float* brow = Wm + (size_t)(n0 + li) * Hh;

    unsigned long long acc[4][2];
    #pragma unroll
    for (int m = 0; m < 4; m++) { acc[m][0] = 0ull; acc[m][1] = 0ull; }

    for (int k0 = 0; k0 < Hh; k0 += BK) {
        float4 av = *(const float4*)(arow + k0 + lk);
        float4 bv = *(const float4*)(brow + k0 + lk);
        As[lk + 0][li] = av.x; As[lk + 1][li] = av.y; As[lk + 2][li] = av.z; As[lk + 3][li] = av.w;
        Bs[lk + 0][li] = bv.x; Bs[lk + 1][li] = bv.y; Bs[lk + 2][li] = bv.z; Bs[lk + 3][li] = bv.w;
        __syncthreads();
        #pragma unroll
        for (int k = 0; k < BK; k++) {
            float4 a = *(const float4*)&As[k][ty * 4];
            const unsigned long long* bp = (const unsigned long long*)&Bs[k][tx * 4];
            unsigned long long b01 = bp[0], b23 = bp[1];
            #pragma unroll
            for (int m = 0; m < 4; m++) {
                unsigned long long am2 = dup_f32(((const float*)&a)[m]);
                asm("fma.rn.f32x2 %0, %1, %2, %0;" : "+l"(acc[m][0]) : "l"(am2), "l"(b01));
                asm("fma.rn.f32x2 %0, %1, %2, %0;" : "+l"(acc[m][1]) : "l"(am2), "l"(b23));
            }
        }
        __syncthreads();
    }
    int gr = m0 + ty * 4, gc = n0 + tx * 4;
    float4 bv = *(const float4*)(bias + gc);
    #pragma unroll
    for (int m = 0; m < 4; m++) {
        unsigned lo0, hi0, lo1, hi1;
        asm("mov.b64 {%0, %1}, %2;" : "=r"(lo0), "=r"(hi0) : "l"(acc[m][0]));
        asm("mov.b64 {%0, %1}, %2;" : "=r"(lo1), "=r"(hi1) : "l"(acc[m][1]));
        float4 out;
        out.x = __uint_as_float(lo0) + bv.x;
        out.y = __uint_as_float(hi0) + bv.y;
        out.z = __uint_as_float(lo1) + bv.z;
        out.w = __uint_as_float(hi1) + bv.w;
        *(float4*)&g_y[(size_t)(gr + m) * Hh + gc] = out;
    }
}

// ---------------- kernel 4: per-(b,l) dot / norm / exp ----------------
__global__ void reduce_kernel(const int* __restrict__ labels, const int* __restrict__ events) {
    __shared__ float sdot[4], snn[4];
    int rr = blockIdx.x;
    int b = rr >> 7;
    int t = threadIdx.x;       // 128 threads
    const float4* y4 = (const float4*)(g_y + (size_t)rr * Hh);
    const float4* x4 = (const float4*)(g_x + (size_t)b * Hh);
    float dot = 0.f, nn = 0.f;
    #pragma unroll
    for (int i = t; i < Hh / 4; i += 128) {
        float4 yv = y4[i], xv = x4[i];
        dot += yv.x * xv.x + yv.y * xv.y + yv.z * xv.z + yv.w * xv.w;
        nn  += yv.x * yv.x + yv.y * yv.y + yv.z * yv.z + yv.w * yv.w;
    }
    #pragma unroll
    for (int d = 16; d > 0; d >>= 1) {
        dot += __shfl_xor_sync(0xffffffffu, dot, d);
        nn  += __shfl_xor_sync(0xffffffffu, nn, d);
    }
    int w = t >> 5;
    if ((t & 31) == 0) { sdot[w] = dot; snn[w] = nn; }
    __syncthreads();
    if (t == 0) {
        float D = sdot[0] + sdot[1] + sdot[2] + sdot[3];
        float N = snn[0] + snn[1] + snn[2] + snn[3];
        float yn = sqrtf(N);
        float denom = fmaxf(g_xn[b] * yn, 1e-8f);
        float e = expf(D / denom);
        g_elab[rr] = e * (float)labels[rr];
        g_eev[rr]  = e * (float)events[rr];
    }
}

// ---------------- kernel 5: final scalar ----------------
__global__ void final_kernel(float* __restrict__ out) {
    int t = threadIdx.x;       // 32 threads
    float loss = 0.f;
    if (t < Bb) {
        float num = 0.f, den = 0.f;
        for (int l = 0; l < Ll; l++) {
            num += g_elab[t * Ll + l];
            den += g_eev[t * Ll + l];
        }
        loss = logf(den) - logf(num);   // == -log(num/den)
    }
    #pragma unroll
    for (int d = 16; d > 0; d >>= 1) loss += __shfl_xor_sync(0xffffffffu, loss, d);
    if (t == 0) out[0] = loss / (float)Bb;
}

// ---------------- launcher ----------------
extern "C" void kernel_launch(void* const* d_in, const int* in_sizes, int n_in,
                              void* d_out, int out_size) {
    const int*   ids    = (const int*)d_in[0];   // int64 or int32 — detected on device
    const float* q      = (const float*)d_in[1];
    const float* seq    = (const float*)d_in[2];
    const int*   events = (const int*)d_in[3];
    const int*   labels = (const int*)d_in[4];
    const int*   offs   = (const int*)d_in[5];   // int64 or int32 — same flag
    const float* Wm     = (const float*)d_in[7];
    const float* bias   = (const float*)d_in[8];

    prep_kernel<<<1, 256>>>(ids, offs);
    xproj_kernel<<<Bb, 256>>>(q, Wm, bias);
    gemm_kernel<<<dim3(Hh / BN, Mm / BM), 256>>>(seq, Wm, bias);
    reduce_kernel<<<Mm, 128>>>(labels, events);
    final_kernel<<<1, 32>>>((float*)d_out);
}

// round 2
// speedup vs baseline: 1.4779x; 1.4779x over previous
#include <cuda_runtime.h>
#include <cstdint>

#define MASK_ID 50264
#define Bb 16
#define Ss 2048
#define Hh 1024
#define Ll 128
#define Mm (Bb*Ll)   // 2048

// ---------------- device scratch (static allocation only) ----------------
__device__ int   g_maskpos[Bb];
__device__ int   g_off[Ll];
__device__ float g_x[Bb*Hh];
__device__ float g_y[(size_t)Mm*Hh];     // 8 MB projected ys
__device__ float g_elab[Mm];
__device__ float g_eev[Mm];

// ---------------- kernel 1: dtype detect + mask_pos + offsets (16 blocks) ----------------
__global__ void prep_kernel(const int* __restrict__ ids_w, const int* __restrict__ off_w) {
    __shared__ int s_flag;
    __shared__ int s_min[256];
    int b = blockIdx.x, t = threadIdx.x;
    if (t == 0) s_flag = 0;
    __syncthreads();
    // Detect int64 vs int32 on the FIRST 4096 words (valid in both layouts):
    // int64 layout -> odd words all zero (ids < 2^31).
    int nz = 0;
    for (int i = t; i < 2048; i += 256) nz |= ids_w[2 * i + 1];
    if (nz) atomicOr(&s_flag, 1);
    __syncthreads();
    const bool is64 = (s_flag == 0);

    if (b == 0 && t < Ll) {
        g_off[t] = is64 ? (int)((const long long*)off_w)[t] : off_w[t];
    }

    const long long* ids64 = (const long long*)ids_w;
    int mi = 0x7fffffff;
    for (int s = t; s < Ss; s += 256) {
        long long v = is64 ? ids64[(size_t)b * Ss + s] : (long long)ids_w[b * Ss + s];
        if (v == MASK_ID && s < mi) mi = s;
    }
    s_min[t] = mi;
    __syncthreads();
    for (int w = 128; w > 0; w >>= 1) {
        if (t < w) s_min[t] = min(s_min[t], s_min[t + w]);
        __syncthreads();
    }
    if (t == 0) g_maskpos[b] = (s_min[0] == 0x7fffffff) ? 0 : s_min[0];
}

// ---------------- kernel 2: project x rows (16 x 1024), 128 blocks ----------------
// grid (8 col-chunks, 16 batches), 128 threads. Each warp computes 32 outputs.
__global__ void xproj_kernel(const float* __restrict__ q, const float* __restrict__ Wm,
                             const float* __restrict__ bias) {
    __shared__ float v[Hh];
    int b = blockIdx.y, chunk = blockIdx.x, t = threadIdx.x;
    int mp = g_maskpos[b];
    const float4* src = (const float4*)(q + ((size_t)b * Ss + mp) * Hh);
    ((float4*)v)[t]       = src[t];
    ((float4*)v)[t + 128] = src[t + 128];
    __syncthreads();
    int w = t >> 5, lane = t & 31;
    for (int oi = 0; oi < 32; oi++) {
        int o = chunk * 128 + w * 32 + oi;
        const float* wr = Wm + (size_t)o * Hh;
        float s = 0.f;
        #pragma unroll
        for (int h = lane * 4; h < Hh; h += 128) {
            float4 wv = *(const float4*)(wr + h);
            float4 vv = *(const float4*)(v + h);
            s += wv.x * vv.x + wv.y * vv.y + wv.z * vv.z + wv.w * vv.w;
        }
        #pragma unroll
        for (int d = 16; d > 0; d >>= 1) s += __shfl_xor_sync(0xffffffffu, s, d);
        if (lane == 0) g_x[b * Hh + o] = s + bias[o];
    }
}

// ---------------- kernel 3: gathered SGEMM, 128x128x8 tiles, f32x2, dup-A smem ----------------
#define BM 128
#define BN 128
#define BK 8

__global__ __launch_bounds__(256, 1) void gemm_kernel(const float* __restrict__ seq,
                                                      const float* __restrict__ Wm,
                                                      const float* __restrict__ bias) {
    __shared__ float Asd[2][BK][2 * BM];   // A values duplicated: [k][2m]=[k][2m+1]=A
    __shared__ float Bs[2][BK][BN];
    int t = threadIdx.x;
    int tx = t & 15, ty = t >> 4;
    int m0 = blockIdx.y * BM, n0 = blockIdx.x * BN;

    // loaders: each thread loads one float4 of A and one of B per tile
    int lrow = t >> 1;
    int lkq = (t & 1) * 4;
    int r = m0 + lrow;
    const float* arow = seq + ((size_t)(r >> 7) * Ss + g_off[r & 127]) * Hh + lkq;
    const float* brow = Wm + (size_t)(n0 + lrow) * Hh + lkq;

    // prologue: tile 0 -> buffer 0
    {
        float4 av = *(const float4*)arow;
        float4 bv = *(const float4*)brow;
        #pragma unroll
        for (int i = 0; i < 4; i++) {
            float vv = ((const float*)&av)[i];
            *(float2*)&Asd[0][lkq + i][2 * lrow] = make_float2(vv, vv);
            Bs[0][lkq + i][lrow] = ((const float*)&bv)[i];
        }
    }
    __syncthreads();

    unsigned long long acc[8][4];
    #pragma unroll
    for (int mi = 0; mi < 8; mi++)
        #pragma unroll
        for (int nj = 0; nj < 4; nj++) acc[mi][nj] = 0ull;

    int buf = 0;
    for (int k0 = BK; k0 < Hh; k0 += BK) {
        float4 av = *(const float4*)(arow + k0);
        float4 bv = *(const float4*)(brow + k0);
        #pragma unroll
        for (int k = 0; k < BK; k++) {
            float4 ar[4];
            ar[0] = *(const float4*)&Asd[buf][k][ty * 16];
            ar[1] = *(const float4*)&Asd[buf][k][ty * 16 + 4];
            ar[2] = *(const float4*)&Asd[buf][k][ty * 16 + 8];
            ar[3] = *(const float4*)&Asd[buf][k][ty * 16 + 12];
            float4 br[2];
            br[0] = *(const float4*)&Bs[buf][k][tx * 8];
            br[1] = *(const float4*)&Bs[buf][k][tx * 8 + 4];
            const unsigned long long* ap = (const unsigned long long*)ar;
            const unsigned long long* bp = (const unsigned long long*)br;
            #pragma unroll
            for (int mi = 0; mi < 8; mi++)
                #pragma unroll
                for (int nj = 0; nj < 4; nj++)
                    asm("fma.rn.f32x2 %0, %1, %2, %0;"
                        : "+l"(acc[mi][nj]) : "l"(ap[mi]), "l"(bp[nj]));
        }
        buf ^= 1;
        #pragma unroll
        for (int i = 0; i < 4; i++) {
            float vv = ((const float*)&av)[i];
            *(float2*)&Asd[buf][lkq + i][2 * lrow] = make_float2(vv, vv);
            Bs[buf][lkq + i][lrow] = ((const float*)&bv)[i];
        }
        __syncthreads();
    }
    // final tile
    #pragma unroll
    for (int k = 0; k < BK; k++) {
        float4 ar[4];
        ar[0] = *(const float4*)&Asd[buf][k][ty * 16];
        ar[1] = *(const float4*)&Asd[buf][k][ty * 16 + 4];
        ar[2] = *(const float4*)&Asd[buf][k][ty * 16 + 8];
        ar[3] = *(const float4*)&Asd[buf][k][ty * 16 + 12];
        float4 br[2];
        br[0] = *(const float4*)&Bs[buf][k][tx * 8];
        br[1] = *(const float4*)&Bs[buf][k][tx * 8 + 4];
        const unsigned long long* ap = (const unsigned long long*)ar;
        const unsigned long long* bp = (const unsigned long long*)br;
        #pragma unroll
        for (int mi = 0; mi < 8; mi++)
            #pragma unroll
            for (int nj = 0; nj < 4; nj++)
                asm("fma.rn.f32x2 %0, %1, %2, %0;"
                    : "+l"(acc[mi][nj]) : "l"(ap[mi]), "l"(bp[nj]));
    }

    // epilogue: add bias, store
    int gc = n0 + tx * 8;
    float4 bias0 = *(const float4*)(bias + gc);
    float4 bias1 = *(const float4*)(bias + gc + 4);
    #pragma unroll
    for (int mi = 0; mi < 8; mi++) {
        int gr = m0 + ty * 8 + mi;
        unsigned lo, hi;
        float4 o0, o1;
        asm("mov.b64 {%0, %1}, %2;" : "=r"(lo), "=r"(hi) : "l"(acc[mi][0]));
        o0.x = __uint_as_float(lo) + bias0.x; o0.y = __uint_as_float(hi) + bias0.y;
        asm("mov.b64 {%0, %1}, %2;" : "=r"(lo), "=r"(hi) : "l"(acc[mi][1]));
        o0.z = __uint_as_float(lo) + bias0.z; o0.w = __uint_as_float(hi) + bias0.w;
        asm("mov.b64 {%0, %1}, %2;" : "=r"(lo), "=r"(hi) : "l"(acc[mi][2]));
        o1.x = __uint_as_float(lo) + bias1.x; o1.y = __uint_as_float(hi) + bias1.y;
        asm("mov.b64 {%0, %1}, %2;" : "=r"(lo), "=r"(hi) : "l"(acc[mi][3]));
        o1.z = __uint_as_float(lo) + bias1.z; o1.w = __uint_as_float(hi) + bias1.w;
        *(float4*)&g_y[(size_t)gr * Hh + gc]     = o0;
        *(float4*)&g_y[(size_t)gr * Hh + gc + 4] = o1;
    }
}

// ---------------- kernel 4: per-(b,l) dot / norms / exp ----------------
__global__ void reduce_kernel(const int* __restrict__ labels, const int* __restrict__ events) {
    __shared__ float sdot[4], snn[4], sxx[4];
    int rr = blockIdx.x;
    int b = rr >> 7;
    int t = threadIdx.x;       // 128 threads
    const float4* y4 = (const float4*)(g_y + (size_t)rr * Hh);
    const float4* x4 = (const float4*)(g_x + (size_t)b * Hh);
    float dot = 0.f, nn = 0.f, xx = 0.f;
    #pragma unroll
    for (int i = t; i < Hh / 4; i += 128) {
        float4 yv = y4[i], xv = x4[i];
        dot += yv.x * xv.x + yv.y * xv.y + yv.z * xv.z + yv.w * xv.w;
        nn  += yv.x * yv.x + yv.y * yv.y + yv.z * yv.z + yv.w * yv.w;
        xx  += xv.x * xv.x + xv.y * xv.y + xv.z * xv.z + xv.w * xv.w;
    }
    #pragma unroll
    for (int d = 16; d > 0; d >>= 1) {
        dot += __shfl_xor_sync(0xffffffffu, dot, d);
        nn  += __shfl_xor_sync(0xffffffffu, nn, d);
        xx  += __shfl_xor_sync(0xffffffffu, xx, d);
    }
    int w = t >> 5;
    if ((t & 31) == 0) { sdot[w] = dot; snn[w] = nn; sxx[w] = xx; }
    __syncthreads();
    if (t == 0) {
        float D = sdot[0] + sdot[1] + sdot[2] + sdot[3];
        float N = snn[0] + snn[1] + snn[2] + snn[3];
        float X = sxx[0] + sxx[1] + sxx[2] + sxx[3];
        float denom = fmaxf(sqrtf(X) * sqrtf(N), 1e-8f);
        float e = expf(D / denom);
        g_elab[rr] = e * (float)labels[rr];
        g_eev[rr]  = e * (float)events[rr];
    }
}

// ---------------- kernel 5: final scalar ----------------
__global__ void final_kernel(float* __restrict__ out) {
    int t = threadIdx.x;       // 32 threads
    float loss = 0.f;
    if (t < Bb) {
        float num = 0.f, den = 0.f;
        for (int l = 0; l < Ll; l++) {
            num += g_elab[t * Ll + l];
            den += g_eev[t * Ll + l];
        }
        loss = logf(den) - logf(num);   // == -log(num/den)
    }
    #pragma unroll
    for (int d = 16; d > 0; d >>= 1) loss += __shfl_xor_sync(0xffffffffu, loss, d);
    if (t == 0) out[0] = loss / (float)Bb;
}

// ---------------- launcher ----------------
extern "C" void kernel_launch(void* const* d_in, const int* in_sizes, int n_in,
                              void* d_out, int out_size) {
    const int*   ids    = (const int*)d_in[0];
    const float* q      = (const float*)d_in[1];
    const float* seq    = (const float*)d_in[2];
    const int*   events = (const int*)d_in[3];
    const int*   labels = (const int*)d_in[4];
    const int*   offs   = (const int*)d_in[5];
    const float* Wm     = (const float*)d_in[7];
    const float* bias   = (const float*)d_in[8];

    prep_kernel<<<Bb, 256>>>(ids, offs);
    xproj_kernel<<<dim3(8, Bb), 128>>>(q, Wm, bias);
    gemm_kernel<<<dim3(Hh / BN, Mm / BM), 256>>>(seq, Wm, bias);
    reduce_kernel<<<Mm, 128>>>(labels, events);
    final_kernel<<<1, 32>>>((float*)d_out);
}

// round 4
// speedup vs baseline: 3.1312x; 2.1187x over previous
#include <cuda_runtime.h>
#include <cuda_bf16.h>
#include <cstdint>

#define MASK_ID 50264
#define Bb 16
#define Ss 2048
#define Hh 1024
#define Ll 128
#define Mm (Bb*Ll)      // 2048

// ---------------- device scratch ----------------
__device__ int   g_maskpos[Bb];
__device__ int   g_off[Ll];
__device__ float g_x[Bb*Hh];
__device__ float g_y[(size_t)Mm*Hh];
__device__ float g_elab[Mm];
__device__ float g_eev[Mm];

// ---------------- kernel 1: dtype detect + mask_pos + offsets ----------------
__global__ void prep_kernel(const int* __restrict__ ids_w, const int* __restrict__ off_w) {
    __shared__ int s_flag;
    __shared__ int s_min[256];
    int b = blockIdx.x, t = threadIdx.x;
    if (t == 0) s_flag = 0;
    __syncthreads();
    int nz = 0;
    for (int i = t; i < 2048; i += 256) nz |= ids_w[2 * i + 1];
    if (nz) atomicOr(&s_flag, 1);
    __syncthreads();
    const bool is64 = (s_flag == 0);
    if (b == 0 && t < Ll)
        g_off[t] = is64 ? (int)((const long long*)off_w)[t] : off_w[t];
    const long long* ids64 = (const long long*)ids_w;
    int mi = 0x7fffffff;
    for (int s = t; s < Ss; s += 256) {
        long long v = is64 ? ids64[(size_t)b * Ss + s] : (long long)ids_w[b * Ss + s];
        if (v == MASK_ID && s < mi) mi = s;
    }
    s_min[t] = mi;
    __syncthreads();
    for (int w = 128; w > 0; w >>= 1) {
        if (t < w) s_min[t] = min(s_min[t], s_min[t + w]);
        __syncthreads();
    }
    if (t == 0) g_maskpos[b] = (s_min[0] == 0x7fffffff) ? 0 : s_min[0];
}

// ---------------- kernel 2: x projection (fp32, 16 rows) ----------------
__global__ void xproj_kernel(const float* __restrict__ q, const float* __restrict__ Wm,
                             const float* __restrict__ bias) {
    __shared__ float v[Hh];
    int b = blockIdx.y, chunk = blockIdx.x, t = threadIdx.x;
    int mp = g_maskpos[b];
    const float4* src = (const float4*)(q + ((size_t)b * Ss + mp) * Hh);
    ((float4*)v)[t]       = src[t];
    ((float4*)v)[t + 128] = src[t + 128];
    __syncthreads();
    int w = t >> 5, lane = t & 31;
    for (int oi = 0; oi < 32; oi++) {
        int o = chunk * 128 + w * 32 + oi;
        const float* wr = Wm + (size_t)o * Hh;
        float s = 0.f;
        #pragma unroll
        for (int h = lane * 4; h < Hh; h += 128) {
            float4 wv = *(const float4*)(wr + h);
            float4 vv = *(const float4*)(v + h);
            s += wv.x * vv.x + wv.y * vv.y + wv.z * vv.z + wv.w * vv.w;
        }
        #pragma unroll
        for (int d = 16; d > 0; d >>= 1) s += __shfl_xor_sync(0xffffffffu, s, d);
        if (lane == 0) g_x[b * Hh + o] = s + bias[o];
    }
}

// ---------------- kernel 3: HMMA split-bf16 GEMM ----------------
// Y[m,n] = sum_k A[m,k] W[n,k] + b[n], A gathered rows of seq.
// Split each f32 into bf16 hi+lo; accumulate hi*hi + lo*hi + hi*lo in f32 HMMA.
#define GM 128
#define GN 128
#define GK 32
#define NC (Hh / GK)     // 32
#define SP 40            // padded smem row stride (bf16 units): conflict-free
// per-buffer bf16 offsets
#define AHI 0
#define ALO (128*SP)
#define BHI (2*128*SP)
#define BLO (3*128*SP)
#define BUFS (4*128*SP)          // 20480 bf16 per buffer
#define SMEM_BYTES (2*BUFS*2)    // 81920 B

__device__ __forceinline__ void mma16816(float* d, const uint32_t* a, const uint32_t* b) {
    asm volatile("mma.sync.aligned.m16n8k16.row.col.f32.bf16.bf16.f32 "
                 "{%0,%1,%2,%3},{%4,%5,%6,%7},{%8,%9},{%0,%1,%2,%3};"
                 : "+f"(d[0]), "+f"(d[1]), "+f"(d[2]), "+f"(d[3])
                 : "r"(a[0]), "r"(a[1]), "r"(a[2]), "r"(a[3]), "r"(b[0]), "r"(b[1]));
}
__device__ __forceinline__ uint32_t lds_u32(const __nv_bfloat16* p) {
    return *(const uint32_t*)p;
}

__global__ __launch_bounds__(256, 1) void gemm_mma(const float* __restrict__ seq,
                                                   const float* __restrict__ Wm,
                                                   const float* __restrict__ bias) {
    extern __shared__ __align__(16) __nv_bfloat16 sm[];
    int t = threadIdx.x, wid = t >> 5, lane = t & 31;
    int wm = wid >> 2, wn = wid & 3;            // 2 x 4 warp grid
    int m0 = blockIdx.y * GM, n0 = blockIdx.x * GN;
    int g = lane >> 2, tq = lane & 3;

    // loader slots: 4 float4 of A and 4 of B per thread per chunk
    const float* aptr[4];
    const float* bptr[4];
    int arow_[4], aq_[4];
    #pragma unroll
    for (int p = 0; p < 4; p++) {
        int j = t + p * 256;
        int row = j >> 3, qq = j & 7;
        arow_[p] = row; aq_[p] = qq;
        int r = m0 + row;
        aptr[p] = seq + ((size_t)(r >> 7) * Ss + g_off[r & 127]) * Hh + qq * 4;
        bptr[p] = Wm + (size_t)(n0 + row) * Hh + qq * 4;
    }

    float acc[4][4][4];
    #pragma unroll
    for (int mt = 0; mt < 4; mt++)
        #pragma unroll
        for (int nt = 0; nt < 4; nt++)
            #pragma unroll
            for (int e = 0; e < 4; e++) acc[mt][nt][e] = 0.f;

    float4 av[4], bv[4];
    #pragma unroll
    for (int p = 0; p < 4; p++) { av[p] = *(const float4*)aptr[p]; bv[p] = *(const float4*)bptr[p]; }

    int buf = 0;
    for (int c = 0; c < NC; c++) {
        // convert + STS current regs -> buf
        __nv_bfloat16* sb = sm + buf * BUFS;
        #pragma unroll
        for (int p = 0; p < 4; p++) {
            int off = arow_[p] * SP + aq_[p] * 4;
            const float* f = (const float*)&av[p];
            __nv_bfloat162 h0 = __float22bfloat162_rn(make_float2(f[0], f[1]));
            __nv_bfloat162 h1 = __float22bfloat162_rn(make_float2(f[2], f[3]));
            __nv_bfloat162 l0 = __float22bfloat162_rn(make_float2(
                f[0] - __bfloat162float(__low2bfloat16(h0)), f[1] - __bfloat162float(__high2bfloat16(h0))));
            __nv_bfloat162 l1 = __float22bfloat162_rn(make_float2(
                f[2] - __bfloat162float(__low2bfloat16(h1)), f[3] - __bfloat162float(__high2bfloat16(h1))));
            *(__nv_bfloat162*)(sb + AHI + off)     = h0;
            *(__nv_bfloat162*)(sb + AHI + off + 2) = h1;
            *(__nv_bfloat162*)(sb + ALO + off)     = l0;
            *(__nv_bfloat162*)(sb + ALO + off + 2) = l1;
            f = (const float*)&bv[p];
            h0 = __float22bfloat162_rn(make_float2(f[0], f[1]));
            h1 = __float22bfloat162_rn(make_float2(f[2], f[3]));
            l0 = __float22bfloat162_rn(make_float2(
                f[0] - __bfloat162float(__low2bfloat16(h0)), f[1] - __bfloat162float(__high2bfloat16(h0))));
            l1 = __float22bfloat162_rn(make_float2(
                f[2] - __bfloat162float(__low2bfloat16(h1)), f[3] - __bfloat162float(__high2bfloat16(h1))));
            *(__nv_bfloat162*)(sb + BHI + off)     = h0;
            *(__nv_bfloat162*)(sb + BHI + off + 2) = h1;
            *(__nv_bfloat162*)(sb + BLO + off)     = l0;
            *(__nv_bfloat162*)(sb + BLO + off + 2) = l1;
        }
        __syncthreads();
        // prefetch next chunk
        if (c + 1 < NC) {
            #pragma unroll
            for (int p = 0; p < 4; p++) {
                av[p] = *(const float4*)(aptr[p] + (c + 1) * GK);
                bv[p] = *(const float4*)(bptr[p] + (c + 1) * GK);
            }
        }
        // MMA over this chunk: 2 k-steps of 16
        #pragma unroll
        for (int ks = 0; ks < 2; ks++) {
            int kb = ks * 16 + tq * 2;
            uint32_t bh[4][2], bl[4][2];
            #pragma unroll
            for (int nt = 0; nt < 4; nt++) {
                int nrow = wn * 32 + nt * 8 + g;
                bh[nt][0] = lds_u32(sb + BHI + nrow * SP + kb);
                bh[nt][1] = lds_u32(sb + BHI + nrow * SP + kb + 8);
                bl[nt][0] = lds_u32(sb + BLO + nrow * SP + kb);
                bl[nt][1] = lds_u32(sb + BLO + nrow * SP + kb + 8);
            }
            #pragma unroll
            for (int mt = 0; mt < 4; mt++) {
                int mrow = wm * 64 + mt * 16 + g;
                uint32_t ah[4], al[4];
                ah[0] = lds_u32(sb + AHI + mrow * SP + kb);
                ah[1] = lds_u32(sb + AHI + (mrow + 8) * SP + kb);
                ah[2] = lds_u32(sb + AHI + mrow * SP + kb + 8);
                ah[3] = lds_u32(sb + AHI + (mrow + 8) * SP + kb + 8);
                al[0] = lds_u32(sb + ALO + mrow * SP + kb);
                al[1] = lds_u32(sb + ALO + (mrow + 8) * SP + kb);
                al[2] = lds_u32(sb + ALO + mrow * SP + kb + 8);
                al[3] = lds_u32(sb + ALO + (mrow + 8) * SP + kb + 8);
                #pragma unroll
                for (int nt = 0; nt < 4; nt++) {
                    mma16816(acc[mt][nt], ah, bh[nt]);
                    mma16816(acc[mt][nt], al, bh[nt]);
                    mma16816(acc[mt][nt], ah, bl[nt]);
                }
            }
        }
        buf ^= 1;
    }

    // epilogue
    #pragma unroll
    for (int mt = 0; mt < 4; mt++) {
        #pragma unroll
        for (int nt = 0; nt < 4; nt++) {
            int gr = m0 + wm * 64 + mt * 16 + g;
            int gc = n0 + wn * 32 + nt * 8 + tq * 2;
            float b0 = bias[gc], b1 = bias[gc + 1];
            float2 o0 = make_float2(acc[mt][nt][0] + b0, acc[mt][nt][1] + b1);
            float2 o1 = make_float2(acc[mt][nt][2] + b0, acc[mt][nt][3] + b1);
            *(float2*)&g_y[(size_t)gr * Hh + gc]       = o0;
            *(float2*)&g_y[(size_t)(gr + 8) * Hh + gc] = o1;
        }
    }
}

// ---------------- kernel 4: per-(b,l) dot / norms / exp ----------------
__global__ void reduce_kernel(const int* __restrict__ labels, const int* __restrict__ events) {
    __shared__ float sdot[4], snn[4], sxx[4];
    int rr = blockIdx.x;
    int b = rr >> 7;
    int t = threadIdx.x;
    const float4* y4 = (const float4*)(g_y + (size_t)rr * Hh);
    const float4* x4 = (const float4*)(g_x + (size_t)b * Hh);
    float dot = 0.f, nn = 0.f, xx = 0.f;
    #pragma unroll
    for (int i = t; i < Hh / 4; i += 128) {
        float4 yv = y4[i], xv = x4[i];
        dot += yv.x * xv.x + yv.y * xv.y + yv.z * xv.z + yv.w * xv.w;
        nn  += yv.x * yv.x + yv.y * yv.y + yv.z * yv.z + yv.w * yv.w;
        xx  += xv.x * xv.x + xv.y * xv.y + xv.z * xv.z + xv.w * xv.w;
    }
    #pragma unroll
    for (int d = 16; d > 0; d >>= 1) {
        dot += __shfl_xor_sync(0xffffffffu, dot, d);
        nn  += __shfl_xor_sync(0xffffffffu, nn, d);
        xx  += __shfl_xor_sync(0xffffffffu, xx, d);
    }
    int w = t >> 5;
    if ((t & 31) == 0) { sdot[w] = dot; snn[w] = nn; sxx[w] = xx; }
    __syncthreads();
    if (t == 0) {
        float D = sdot[0] + sdot[1] + sdot[2] + sdot[3];
        float N = snn[0] + snn[1] + snn[2] + snn[3];
        float X = sxx[0] + sxx[1] + sxx[2] + sxx[3];
        float denom = fmaxf(sqrtf(X) * sqrtf(N), 1e-8f);
        float e = expf(D / denom);
        g_elab[rr] = e * (float)labels[rr];
        g_eev[rr]  = e * (float)events[rr];
    }
}

// ---------------- kernel 5: final scalar ----------------
__global__ void final_kernel(float* __restrict__ out) {
    int t = threadIdx.x;
    float loss = 0.f;
    if (t < Bb) {
        float num = 0.f, den = 0.f;
        for (int l = 0; l < Ll; l++) {
            num += g_elab[t * Ll + l];
            den += g_eev[t * Ll + l];
        }
        loss = logf(den) - logf(num);
    }
    #pragma unroll
    for (int d = 16; d > 0; d >>= 1) loss += __shfl_xor_sync(0xffffffffu, loss, d);
    if (t == 0) out[0] = loss / (float)Bb;
}

// ---------------- launcher ----------------
extern "C" void kernel_launch(void* const* d_in, const int* in_sizes, int n_in,
                              void* d_out, int out_size) {
    const int*   ids    = (const int*)d_in[0];
    const float* q      = (const float*)d_in[1];
    const float* seq    = (const float*)d_in[2];
    const int*   events = (const int*)d_in[3];
    const int*   labels = (const int*)d_in[4];
    const int*   offs   = (const int*)d_in[5];
    const float* Wm     = (const float*)d_in[7];
    const float* bias   = (const float*)d_in[8];

    cudaFuncSetAttribute(gemm_mma, cudaFuncAttributeMaxDynamicSharedMemorySize, SMEM_BYTES);

    prep_kernel<<<Bb, 256>>>(ids, offs);
    xproj_kernel<<<dim3(8, Bb), 128>>>(q, Wm, bias);
    gemm_mma<<<dim3(Hh / GN, Mm / GM), 256, SMEM_BYTES>>>(seq, Wm, bias);
    reduce_kernel<<<Mm, 128>>>(labels, events);
    final_kernel<<<1, 32>>>((float*)d_out);
}

// round 5
// speedup vs baseline: 3.2267x; 1.0305x over previous
#include <cuda_runtime.h>
#include <cuda_bf16.h>
#include <cstdint>

#define MASK_ID 50264
#define Bb 16
#define Ss 2048
#define Hh 1024
#define Ll 128
#define Mm (Bb*Ll)      // 2048
#define NBLK 8          // GEMM column blocks

// ---------------- device scratch ----------------
__device__ int   g_maskpos[Bb];
__device__ int   g_off[Ll];
__device__ float g_x[Bb*Hh];
__device__ float g_dotp[NBLK][Mm];
__device__ float g_nnp[NBLK][Mm];
__device__ float g_lossb[Bb];

// ---------------- kernel 1: dtype detect + mask_pos + offsets ----------------
__global__ void prep_kernel(const int* __restrict__ ids_w, const int* __restrict__ off_w) {
    __shared__ int s_flag;
    __shared__ int s_min[256];
    int b = blockIdx.x, t = threadIdx.x;
    if (t == 0) s_flag = 0;
    __syncthreads();
    int nz = 0;
    for (int i = t; i < 2048; i += 256) nz |= ids_w[2 * i + 1];
    if (nz) atomicOr(&s_flag, 1);
    __syncthreads();
    const bool is64 = (s_flag == 0);
    if (b == 0 && t < Ll)
        g_off[t] = is64 ? (int)((const long long*)off_w)[t] : off_w[t];
    const long long* ids64 = (const long long*)ids_w;
    int mi = 0x7fffffff;
    for (int s = t; s < Ss; s += 256) {
        long long v = is64 ? ids64[(size_t)b * Ss + s] : (long long)ids_w[b * Ss + s];
        if (v == MASK_ID && s < mi) mi = s;
    }
    s_min[t] = mi;
    __syncthreads();
    for (int w = 128; w > 0; w >>= 1) {
        if (t < w) s_min[t] = min(s_min[t], s_min[t + w]);
        __syncthreads();
    }
    if (t == 0) g_maskpos[b] = (s_min[0] == 0x7fffffff) ? 0 : s_min[0];
}

// ---------------- kernel 2: x projection (fp32, 16 rows) ----------------
__global__ void xproj_kernel(const float* __restrict__ q, const float* __restrict__ Wm,
                             const float* __restrict__ bias) {
    __shared__ float v[Hh];
    int b = blockIdx.y, chunk = blockIdx.x, t = threadIdx.x;
    int mp = g_maskpos[b];
    const float4* src = (const float4*)(q + ((size_t)b * Ss + mp) * Hh);
    ((float4*)v)[t]       = src[t];
    ((float4*)v)[t + 128] = src[t + 128];
    __syncthreads();
    int w = t >> 5, lane = t & 31;
    for (int oi = 0; oi < 32; oi++) {
        int o = chunk * 128 + w * 32 + oi;
        const float* wr = Wm + (size_t)o * Hh;
        float s = 0.f;
        #pragma unroll
        for (int h = lane * 4; h < Hh; h += 128) {
            float4 wv = *(const float4*)(wr + h);
            float4 vv = *(const float4*)(v + h);
            s += wv.x * vv.x + wv.y * vv.y + wv.z * vv.z + wv.w * vv.w;
        }
        #pragma unroll
        for (int d = 16; d > 0; d >>= 1) s += __shfl_xor_sync(0xffffffffu, s, d);
        if (lane == 0) g_x[b * Hh + o] = s + bias[o];
    }
}

// ---------------- kernel 3: HMMA split-bf16 GEMM with fused dot/norm epilogue ----------------
#define GM 128
#define GN 128
#define GK 32
#define NC (Hh / GK)     // 32
#define SP 40            // padded smem row stride (bf16)
#define AHI 0
#define ALO (128*SP)
#define BHI (2*128*SP)
#define BLO (3*128*SP)
#define BUFS (4*128*SP)
#define SMEM_BYTES (2*BUFS*2)    // 81920 B dynamic

__device__ __forceinline__ void mma16816(float* d, const uint32_t* a, const uint32_t* b) {
    asm volatile("mma.sync.aligned.m16n8k16.row.col.f32.bf16.bf16.f32 "
                 "{%0,%1,%2,%3},{%4,%5,%6,%7},{%8,%9},{%0,%1,%2,%3};"
                 : "+f"(d[0]), "+f"(d[1]), "+f"(d[2]), "+f"(d[3])
                 : "r"(a[0]), "r"(a[1]), "r"(a[2]), "r"(a[3]), "r"(b[0]), "r"(b[1]));
}
__device__ __forceinline__ uint32_t lds_u32(const __nv_bfloat16* p) {
    return *(const uint32_t*)p;
}
__device__ __forceinline__ void conv_sts(__nv_bfloat16* hi, __nv_bfloat16* lo, const float4& v) {
    const float* f = (const float*)&v;
    __nv_bfloat162 h0 = __float22bfloat162_rn(make_float2(f[0], f[1]));
    __nv_bfloat162 h1 = __float22bfloat162_rn(make_float2(f[2], f[3]));
    __nv_bfloat162 l0 = __float22bfloat162_rn(make_float2(
        f[0] - __bfloat162float(__low2bfloat16(h0)), f[1] - __bfloat162float(__high2bfloat16(h0))));
    __nv_bfloat162 l1 = __float22bfloat162_rn(make_float2(
        f[2] - __bfloat162float(__low2bfloat16(h1)), f[3] - __bfloat162float(__high2bfloat16(h1))));
    *(__nv_bfloat162*)(hi)     = h0;
    *(__nv_bfloat162*)(hi + 2) = h1;
    *(__nv_bfloat162*)(lo)     = l0;
    *(__nv_bfloat162*)(lo + 2) = l1;
}

__global__ __launch_bounds__(256, 1) void gemm_mma(const float* __restrict__ seq,
                                                   const float* __restrict__ Wm,
                                                   const float* __restrict__ bias) {
    extern __shared__ __align__(16) __nv_bfloat16 sm[];
    __shared__ float sdot[4][GM], snn[4][GM];
    int t = threadIdx.x, wid = t >> 5, lane = t & 31;
    int wm = wid >> 2, wn = wid & 3;
    int m0 = blockIdx.y * GM, n0 = blockIdx.x * GN;
    int g = lane >> 2, tq = lane & 3;

    const float* aptr[4];
    const float* bptr[4];
    int arow_[4], aq_[4];
    #pragma unroll
    for (int p = 0; p < 4; p++) {
        int j = t + p * 256;
        int row = j >> 3, qq = j & 7;
        arow_[p] = row; aq_[p] = qq;
        int r = m0 + row;
        aptr[p] = seq + ((size_t)(r >> 7) * Ss + g_off[r & 127]) * Hh + qq * 4;
        bptr[p] = Wm + (size_t)(n0 + row) * Hh + qq * 4;
    }

    float acc[4][4][4];
    #pragma unroll
    for (int mt = 0; mt < 4; mt++)
        #pragma unroll
        for (int nt = 0; nt < 4; nt++)
            #pragma unroll
            for (int e = 0; e < 4; e++) acc[mt][nt][e] = 0.f;

    float4 av[4], bv[4];
    #pragma unroll
    for (int p = 0; p < 4; p++) { av[p] = *(const float4*)aptr[p]; bv[p] = *(const float4*)bptr[p]; }
    // prologue: chunk 0 -> buf 0
    {
        __nv_bfloat16* sb = sm;
        #pragma unroll
        for (int p = 0; p < 4; p++) {
            int off = arow_[p] * SP + aq_[p] * 4;
            conv_sts(sb + AHI + off, sb + ALO + off, av[p]);
            conv_sts(sb + BHI + off, sb + BLO + off, bv[p]);
        }
    }
    __syncthreads();

    for (int c = 0; c < NC; c++) {
        if (c + 1 < NC) {
            #pragma unroll
            for (int p = 0; p < 4; p++) {
                av[p] = *(const float4*)(aptr[p] + (c + 1) * GK);
                bv[p] = *(const float4*)(bptr[p] + (c + 1) * GK);
            }
        }
        const __nv_bfloat16* sb = sm + (c & 1) * BUFS;
        #pragma unroll
        for (int ks = 0; ks < 2; ks++) {
            int kb = ks * 16 + tq * 2;
            uint32_t bh[4][2], bl[4][2];
            #pragma unroll
            for (int nt = 0; nt < 4; nt++) {
                int nrow = wn * 32 + nt * 8 + g;
                bh[nt][0] = lds_u32(sb + BHI + nrow * SP + kb);
                bh[nt][1] = lds_u32(sb + BHI + nrow * SP + kb + 8);
                bl[nt][0] = lds_u32(sb + BLO + nrow * SP + kb);
                bl[nt][1] = lds_u32(sb + BLO + nrow * SP + kb + 8);
            }
            #pragma unroll
            for (int mt = 0; mt < 4; mt++) {
                int mrow = wm * 64 + mt * 16 + g;
                uint32_t ah[4], al[4];
                ah[0] = lds_u32(sb + AHI + mrow * SP + kb);
                ah[1] = lds_u32(sb + AHI + (mrow + 8) * SP + kb);
                ah[2] = lds_u32(sb + AHI + mrow * SP + kb + 8);
                ah[3] = lds_u32(sb + AHI + (mrow + 8) * SP + kb + 8);
                al[0] = lds_u32(sb + ALO + mrow * SP + kb);
                al[1] = lds_u32(sb + ALO + (mrow + 8) * SP + kb);
                al[2] = lds_u32(sb + ALO + mrow * SP + kb + 8);
                al[3] = lds_u32(sb + ALO + (mrow + 8) * SP + kb + 8);
                #pragma unroll
                for (int nt = 0; nt < 4; nt++) {
                    mma16816(acc[mt][nt], ah, bh[nt]);
                    mma16816(acc[mt][nt], al, bh[nt]);
                    mma16816(acc[mt][nt], ah, bl[nt]);
                }
            }
        }
        // convert NEXT chunk into the other buffer while tensor pipe is busy
        if (c + 1 < NC) {
            __nv_bfloat16* sw = sm + ((c + 1) & 1) * BUFS;
            #pragma unroll
            for (int p = 0; p < 4; p++) {
                int off = arow_[p] * SP + aq_[p] * 4;
                conv_sts(sw + AHI + off, sw + ALO + off, av[p]);
                conv_sts(sw + BHI + off, sw + BLO + off, bv[p]);
            }
        }
        __syncthreads();
    }

    // fused epilogue: per-row dot(x,y) and ||y||^2 over this CTA's 128 cols
    int b = blockIdx.y;   // GM == Ll: each m-block is one batch
    float xv[4][2], bb[4][2];
    #pragma unroll
    for (int nt = 0; nt < 4; nt++) {
        int gc = n0 + wn * 32 + nt * 8 + tq * 2;
        bb[nt][0] = bias[gc];           bb[nt][1] = bias[gc + 1];
        xv[nt][0] = g_x[b * Hh + gc];   xv[nt][1] = g_x[b * Hh + gc + 1];
    }
    #pragma unroll
    for (int mt = 0; mt < 4; mt++) {
        #pragma unroll
        for (int h = 0; h < 2; h++) {
            float dr = 0.f, nr = 0.f;
            #pragma unroll
            for (int nt = 0; nt < 4; nt++) {
                float y0 = acc[mt][nt][2 * h]     + bb[nt][0];
                float y1 = acc[mt][nt][2 * h + 1] + bb[nt][1];
                dr += y0 * xv[nt][0] + y1 * xv[nt][1];
                nr += y0 * y0 + y1 * y1;
            }
            dr += __shfl_xor_sync(0xffffffffu, dr, 1);
            dr += __shfl_xor_sync(0xffffffffu, dr, 2);
            nr += __shfl_xor_sync(0xffffffffu, nr, 1);
            nr += __shfl_xor_sync(0xffffffffu, nr, 2);
            if (tq == 0) {
                int row = wm * 64 + mt * 16 + h * 8 + g;
                sdot[wn][row] = dr;
                snn[wn][row]  = nr;
            }
        }
    }
    __syncthreads();
    if (t < GM) {
        g_dotp[blockIdx.x][m0 + t] = sdot[0][t] + sdot[1][t] + sdot[2][t] + sdot[3][t];
        g_nnp[blockIdx.x][m0 + t]  = snn[0][t] + snn[1][t] + snn[2][t] + snn[3][t];
    }
}

// ---------------- kernel 4: combine partials, per-batch loss ----------------
__global__ void combine_kernel(const int* __restrict__ labels, const int* __restrict__ events) {
    __shared__ float sred[4];
    __shared__ float s_xn;
    int b = blockIdx.x, t = threadIdx.x;   // 128 threads
    int w = t >> 5, lane = t & 31;
    // ||x_b||
    float xx = 0.f;
    #pragma unroll
    for (int i = t; i < Hh; i += 128) {
        float v = g_x[b * Hh + i];
        xx += v * v;
    }
    #pragma unroll
    for (int d = 16; d > 0; d >>= 1) xx += __shfl_xor_sync(0xffffffffu, xx, d);
    if (lane == 0) sred[w] = xx;
    __syncthreads();
    if (t == 0) s_xn = sqrtf(sred[0] + sred[1] + sred[2] + sred[3]);
    __syncthreads();
    float xn = s_xn;

    int rr = b * Ll + t;
    float dot = 0.f, nn = 0.f;
    #pragma unroll
    for (int p = 0; p < NBLK; p++) { dot += g_dotp[p][rr]; nn += g_nnp[p][rr]; }
    float e = expf(dot / fmaxf(xn * sqrtf(nn), 1e-8f));
    float num = e * (float)labels[rr];
    float den = e * (float)events[rr];
    #pragma unroll
    for (int d = 16; d > 0; d >>= 1) {
        num += __shfl_xor_sync(0xffffffffu, num, d);
        den += __shfl_xor_sync(0xffffffffu, den, d);
    }
    __syncthreads();
    if (lane == 0) { sred[w] = num; }
    __syncthreads();
    float numT = (t == 0) ? (sred[0] + sred[1] + sred[2] + sred[3]) : 0.f;
    __syncthreads();
    if (lane == 0) { sred[w] = den; }
    __syncthreads();
    if (t == 0) {
        float denT = sred[0] + sred[1] + sred[2] + sred[3];
        g_lossb[b] = logf(denT) - logf(numT);
    }
}

// ---------------- kernel 5: final scalar ----------------
__global__ void final_kernel(float* __restrict__ out) {
    int t = threadIdx.x;
    float loss = (t < Bb) ? g_lossb[t] : 0.f;
    #pragma unroll
    for (int d = 16; d > 0; d >>= 1) loss += __shfl_xor_sync(0xffffffffu, loss, d);
    if (t == 0) out[0] = loss / (float)Bb;
}

// ---------------- launcher ----------------
extern "C" void kernel_launch(void* const* d_in, const int* in_sizes, int n_in,
                              void* d_out, int out_size) {
    const int*   ids    = (const int*)d_in[0];
    const float* q      = (const float*)d_in[1];
    const float* seq    = (const float*)d_in[2];
    const int*   events = (const int*)d_in[3];
    const int*   labels = (const int*)d_in[4];
    const int*   offs   = (const int*)d_in[5];
    const float* Wm     = (const float*)d_in[7];
    const float* bias   = (const float*)d_in[8];

    cudaFuncSetAttribute(gemm_mma, cudaFuncAttributeMaxDynamicSharedMemorySize, SMEM_BYTES);

    prep_kernel<<<Bb, 256>>>(ids, offs);
    xproj_kernel<<<dim3(8, Bb), 128>>>(q, Wm, bias);
    gemm_mma<<<dim3(NBLK, Mm / GM), 256, SMEM_BYTES>>>(seq, Wm, bias);
    combine_kernel<<<Bb, 128>>>(labels, events);
    final_kernel<<<1, 32>>>((float*)d_out);
}

// round 6
// speedup vs baseline: 5.5000x; 1.7045x over previous
#include <cuda_runtime.h>
#include <cuda_bf16.h>
#include <cstdint>

#define MASK_ID 50264
#define Bb 16
#define Ss 2048
#define Hh 1024
#define Ll 128
#define Mm (Bb*Ll)      // 2048
#define NBLK 8          // GEMM column blocks
#define ZP 16           // z partials

// ---------------- device scratch ----------------
__device__ int   g_maskpos[Bb];
__device__ int   g_off[Ll];
__device__ float g_x[Bb*Hh];
__device__ float g_zp[ZP][Bb][Hh];   // 1 MB z partials
__device__ float g_z[Bb*Hh];
__device__ float g_xn[Bb];
__device__ float g_xb[Bb];
__device__ float g_dot[Mm];
__device__ float g_nnp[NBLK][Mm];

// ---------------- kernel 1: dtype detect + mask_pos + offsets ----------------
__global__ void prep_kernel(const int* __restrict__ ids_w, const int* __restrict__ off_w) {
    __shared__ int s_flag;
    __shared__ int s_min[256];
    int b = blockIdx.x, t = threadIdx.x;
    if (t == 0) s_flag = 0;
    __syncthreads();
    int nz = 0;
    for (int i = t; i < 2048; i += 256) nz |= ids_w[2 * i + 1];
    if (nz) atomicOr(&s_flag, 1);
    __syncthreads();
    const bool is64 = (s_flag == 0);
    if (b == 0 && t < Ll)
        g_off[t] = is64 ? (int)((const long long*)off_w)[t] : off_w[t];
    const long long* ids64 = (const long long*)ids_w;
    int mi = 0x7fffffff;
    for (int s = t; s < Ss; s += 256) {
        long long v = is64 ? ids64[(size_t)b * Ss + s] : (long long)ids_w[b * Ss + s];
        if (v == MASK_ID && s < mi) mi = s;
    }
    s_min[t] = mi;
    __syncthreads();
    for (int w = 128; w > 0; w >>= 1) {
        if (t < w) s_min[t] = min(s_min[t], s_min[t + w]);
        __syncthreads();
    }
    if (t == 0) g_maskpos[b] = (s_min[0] == 0x7fffffff) ? 0 : s_min[0];
}

// ---------------- kernel 2: x projection (fp32, 16 rows) ----------------
__global__ void xproj_kernel(const float* __restrict__ q, const float* __restrict__ Wm,
                             const float* __restrict__ bias) {
    __shared__ float v[Hh];
    int b = blockIdx.y, chunk = blockIdx.x, t = threadIdx.x;
    int mp = g_maskpos[b];
    const float4* src = (const float4*)(q + ((size_t)b * Ss + mp) * Hh);
    ((float4*)v)[t]       = src[t];
    ((float4*)v)[t + 128] = src[t + 128];
    __syncthreads();
    int w = t >> 5, lane = t & 31;
    for (int oi = 0; oi < 32; oi++) {
        int o = chunk * 128 + w * 32 + oi;
        const float* wr = Wm + (size_t)o * Hh;
        float s = 0.f;
        #pragma unroll
        for (int h = lane * 4; h < Hh; h += 128) {
            float4 wv = *(const float4*)(wr + h);
            float4 vv = *(const float4*)(v + h);
            s += wv.x * vv.x + wv.y * vv.y + wv.z * vv.z + wv.w * vv.w;
        }
        #pragma unroll
        for (int d = 16; d > 0; d >>= 1) s += __shfl_xor_sync(0xffffffffu, s, d);
        if (lane == 0) g_x[b * Hh + o] = s + bias[o];
    }
}

// ---------------- kernel 3: z partials  z[b][h] = sum_o x[b][o] * W[o][h] ----------------
// grid (hc=8, oc=16), 128 threads. W tile 64 x 128 in smem.
__global__ void zcomp_kernel(const float* __restrict__ Wm) {
    __shared__ float sw[64][128];
    __shared__ float sx[16][64];
    int hc = blockIdx.x, oc = blockIdx.y, t = threadIdx.x;
    int o0 = oc * 64, h0 = hc * 128;
    #pragma unroll
    for (int j = 0; j < 16; j++) {
        int idx = t + j * 128;             // 2048 float4 total
        int row = idx >> 5, c4 = idx & 31;
        *(float4*)&sw[row][c4 * 4] = *(const float4*)(Wm + (size_t)(o0 + row) * Hh + h0 + c4 * 4);
    }
    #pragma unroll
    for (int j = 0; j < 8; j++) {
        int idx = t + j * 128;             // 1024 floats
        int b = idx >> 6, o = idx & 63;
        sx[b][o] = g_x[b * Hh + o0 + o];
    }
    __syncthreads();
    float acc[16];
    #pragma unroll
    for (int b = 0; b < 16; b++) acc[b] = 0.f;
    for (int o = 0; o < 64; o++) {
        float wv = sw[o][t];
        #pragma unroll
        for (int b = 0; b < 16; b++) acc[b] += sx[b][o] * wv;
    }
    #pragma unroll
    for (int b = 0; b < 16; b++) g_zp[oc][b][h0 + t] = acc[b];
}

// ---------------- kernel 4: z reduce + per-batch xn, xb ----------------
__global__ void zred_kernel(const float* __restrict__ bias) {
    __shared__ float sxx[8], sxb[8];
    int b = blockIdx.x, t = threadIdx.x;   // 256 threads
    float xx = 0.f, xb = 0.f;
    #pragma unroll
    for (int j = 0; j < 4; j++) {
        int h = t + j * 256;
        float z = 0.f;
        #pragma unroll
        for (int p = 0; p < ZP; p++) z += g_zp[p][b][h];
        g_z[b * Hh + h] = z;
        float xv = g_x[b * Hh + h];
        xx += xv * xv;
        xb += xv * bias[h];
    }
    #pragma unroll
    for (int d = 16; d > 0; d >>= 1) {
        xx += __shfl_xor_sync(0xffffffffu, xx, d);
        xb += __shfl_xor_sync(0xffffffffu, xb, d);
    }
    int w = t >> 5;
    if ((t & 31) == 0) { sxx[w] = xx; sxb[w] = xb; }
    __syncthreads();
    if (t == 0) {
        float X = 0.f, XB = 0.f;
        #pragma unroll
        for (int i = 0; i < 8; i++) { X += sxx[i]; XB += sxb[i]; }
        g_xn[b] = sqrtf(X);
        g_xb[b] = XB;
    }
}

// ---------------- kernel 5: per-row exact dot = a . z + x . b ----------------
__global__ void dotk_kernel(const float* __restrict__ seq) {
    __shared__ float sred[4];
    int r = blockIdx.x, t = threadIdx.x;   // 128 threads
    int b = r >> 7, l = r & 127;
    const float4* a4 = (const float4*)(seq + ((size_t)b * Ss + g_off[l]) * Hh);
    const float4* z4 = (const float4*)(g_z + b * Hh);
    float d = 0.f;
    #pragma unroll
    for (int i = t; i < Hh / 4; i += 128) {
        float4 av = a4[i], zv = z4[i];
        d += av.x * zv.x + av.y * zv.y + av.z * zv.z + av.w * zv.w;
    }
    #pragma unroll
    for (int s = 16; s > 0; s >>= 1) d += __shfl_xor_sync(0xffffffffu, d, s);
    int w = t >> 5;
    if ((t & 31) == 0) sred[w] = d;
    __syncthreads();
    if (t == 0) g_dot[r] = sred[0] + sred[1] + sred[2] + sred[3] + g_xb[b];
}

// ---------------- kernel 6: 1-pass bf16 HMMA GEMM for ||y||^2 partials ----------------
#define GM 128
#define GN 128
#define GK 32
#define NC (Hh / GK)
#define SP 40
#define AHI 0
#define BHI (128*SP)
#define BUFS (2*128*SP)
#define SMEM_BYTES (2*BUFS*2)   // 40960 B

__device__ __forceinline__ void mma16816(float* d, const uint32_t* a, const uint32_t* b) {
    asm volatile("mma.sync.aligned.m16n8k16.row.col.f32.bf16.bf16.f32 "
                 "{%0,%1,%2,%3},{%4,%5,%6,%7},{%8,%9},{%0,%1,%2,%3};"
                 : "+f"(d[0]), "+f"(d[1]), "+f"(d[2]), "+f"(d[3])
                 : "r"(a[0]), "r"(a[1]), "r"(a[2]), "r"(a[3]), "r"(b[0]), "r"(b[1]));
}
__device__ __forceinline__ uint32_t lds_u32(const __nv_bfloat16* p) {
    return *(const uint32_t*)p;
}
__device__ __forceinline__ void conv_hi(__nv_bfloat16* hi, const float4& v) {
    const float* f = (const float*)&v;
    *(__nv_bfloat162*)(hi)     = __float22bfloat162_rn(make_float2(f[0], f[1]));
    *(__nv_bfloat162*)(hi + 2) = __float22bfloat162_rn(make_float2(f[2], f[3]));
}

__global__ __launch_bounds__(256, 1) void gemm_norm(const float* __restrict__ seq,
                                                    const float* __restrict__ Wm,
                                                    const float* __restrict__ bias) {
    extern __shared__ __align__(16) __nv_bfloat16 sm[];
    __shared__ float snn[4][GM];
    int t = threadIdx.x, wid = t >> 5, lane = t & 31;
    int wm = wid >> 2, wn = wid & 3;
    int m0 = blockIdx.y * GM, n0 = blockIdx.x * GN;
    int g = lane >> 2, tq = lane & 3;

    const float* aptr[4];
    const float* bptr[4];
    int arow_[4], aq_[4];
    #pragma unroll
    for (int p = 0; p < 4; p++) {
        int j = t + p * 256;
        int row = j >> 3, qq = j & 7;
        arow_[p] = row; aq_[p] = qq;
        int r = m0 + row;
        aptr[p] = seq + ((size_t)(r >> 7) * Ss + g_off[r & 127]) * Hh + qq * 4;
        bptr[p] = Wm + (size_t)(n0 + row) * Hh + qq * 4;
    }

    float acc[4][4][4];
    #pragma unroll
    for (int mt = 0; mt < 4; mt++)
        #pragma unroll
        for (int nt = 0; nt < 4; nt++)
            #pragma unroll
            for (int e = 0; e < 4; e++) acc[mt][nt][e] = 0.f;

    float4 av[4], bv[4];
    #pragma unroll
    for (int p = 0; p < 4; p++) { av[p] = *(const float4*)aptr[p]; bv[p] = *(const float4*)bptr[p]; }
    {
        __nv_bfloat16* sb = sm;
        #pragma unroll
        for (int p = 0; p < 4; p++) {
            int off = arow_[p] * SP + aq_[p] * 4;
            conv_hi(sb + AHI + off, av[p]);
            conv_hi(sb + BHI + off, bv[p]);
        }
    }
    __syncthreads();

    for (int c = 0; c < NC; c++) {
        if (c + 1 < NC) {
            #pragma unroll
            for (int p = 0; p < 4; p++) {
                av[p] = *(const float4*)(aptr[p] + (c + 1) * GK);
                bv[p] = *(const float4*)(bptr[p] + (c + 1) * GK);
            }
        }
        const __nv_bfloat16* sb = sm + (c & 1) * BUFS;
        #pragma unroll
        for (int ks = 0; ks < 2; ks++) {
            int kb = ks * 16 + tq * 2;
            uint32_t bh[4][2];
            #pragma unroll
            for (int nt = 0; nt < 4; nt++) {
                int nrow = wn * 32 + nt * 8 + g;
                bh[nt][0] = lds_u32(sb + BHI + nrow * SP + kb);
                bh[nt][1] = lds_u32(sb + BHI + nrow * SP + kb + 8);
            }
            #pragma unroll
            for (int mt = 0; mt < 4; mt++) {
                int mrow = wm * 64 + mt * 16 + g;
                uint32_t ah[4];
                ah[0] = lds_u32(sb + AHI + mrow * SP + kb);
                ah[1] = lds_u32(sb + AHI + (mrow + 8) * SP + kb);
                ah[2] = lds_u32(sb + AHI + mrow * SP + kb + 8);
                ah[3] = lds_u32(sb + AHI + (mrow + 8) * SP + kb + 8);
                #pragma unroll
                for (int nt = 0; nt < 4; nt++) mma16816(acc[mt][nt], ah, bh[nt]);
            }
        }
        if (c + 1 < NC) {
            __nv_bfloat16* sw = sm + ((c + 1) & 1) * BUFS;
            #pragma unroll
            for (int p = 0; p < 4; p++) {
                int off = arow_[p] * SP + aq_[p] * 4;
                conv_hi(sw + AHI + off, av[p]);
                conv_hi(sw + BHI + off, bv[p]);
            }
        }
        __syncthreads();
    }

    // epilogue: per-row ||y||^2 partials over this CTA's 128 cols (y = acc + bias)
    float bb[4][2];
    #pragma unroll
    for (int nt = 0; nt < 4; nt++) {
        int gc = n0 + wn * 32 + nt * 8 + tq * 2;
        bb[nt][0] = bias[gc];
        bb[nt][1] = bias[gc + 1];
    }
    #pragma unroll
    for (int mt = 0; mt < 4; mt++) {
        #pragma unroll
        for (int h = 0; h < 2; h++) {
            float nr = 0.f;
            #pragma unroll
            for (int nt = 0; nt < 4; nt++) {
                float y0 = acc[mt][nt][2 * h]     + bb[nt][0];
                float y1 = acc[mt][nt][2 * h + 1] + bb[nt][1];
                nr += y0 * y0 + y1 * y1;
            }
            nr += __shfl_xor_sync(0xffffffffu, nr, 1);
            nr += __shfl_xor_sync(0xffffffffu, nr, 2);
            if (tq == 0) snn[wn][wm * 64 + mt * 16 + h * 8 + g] = nr;
        }
    }
    __syncthreads();
    if (t < GM)
        g_nnp[blockIdx.x][m0 + t] = snn[0][t] + snn[1][t] + snn[2][t] + snn[3][t];
}

// ---------------- kernel 7: combine + final loss (one block) ----------------
__global__ void combine_kernel(const int* __restrict__ labels, const int* __restrict__ events,
                               float* __restrict__ out) {
    __shared__ float s_num[64], s_den[64];
    int t = threadIdx.x;   // 1024 threads
    int w = t >> 5, lane = t & 31;
    float nums[2], dens[2];
    #pragma unroll
    for (int half = 0; half < 2; half++) {
        int r = t + half * 1024;
        int b = r >> 7;
        float nn = 0.f;
        #pragma unroll
        for (int p = 0; p < NBLK; p++) nn += g_nnp[p][r];
        float e = expf(g_dot[r] / fmaxf(g_xn[b] * sqrtf(nn), 1e-8f));
        nums[half] = e * (float)labels[r];
        dens[half] = e * (float)events[r];
    }
    #pragma unroll
    for (int d = 16; d > 0; d >>= 1) {
        nums[0] += __shfl_xor_sync(0xffffffffu, nums[0], d);
        nums[1] += __shfl_xor_sync(0xffffffffu, nums[1], d);
        dens[0] += __shfl_xor_sync(0xffffffffu, dens[0], d);
        dens[1] += __shfl_xor_sync(0xffffffffu, dens[1], d);
    }
    if (lane == 0) {
        s_num[w]      = nums[0];  s_den[w]      = dens[0];   // batch w>>2
        s_num[32 + w] = nums[1];  s_den[32 + w] = dens[1];   // batch 8 + (w>>2)
    }
    __syncthreads();
    if (t < 32) {
        float loss = 0.f;
        if (t < 16) {
            int base = (t < 8) ? 4 * t : 32 + 4 * (t - 8);
            float num = s_num[base] + s_num[base + 1] + s_num[base + 2] + s_num[base + 3];
            float den = s_den[base] + s_den[base + 1] + s_den[base + 2] + s_den[base + 3];
            loss = logf(den) - logf(num);
        }
        #pragma unroll
        for (int d = 16; d > 0; d >>= 1) loss += __shfl_xor_sync(0xffffffffu, loss, d);
        if (t == 0) out[0] = loss / (float)Bb;
    }
}

// ---------------- launcher: forked-stream graph ----------------
extern "C" void kernel_launch(void* const* d_in, const int* in_sizes, int n_in,
                              void* d_out, int out_size) {
    const int*   ids    = (const int*)d_in[0];
    const float* q      = (const float*)d_in[1];
    const float* seq    = (const float*)d_in[2];
    const int*   events = (const int*)d_in[3];
    const int*   labels = (const int*)d_in[4];
    const int*   offs   = (const int*)d_in[5];
    const float* Wm     = (const float*)d_in[7];
    const float* bias   = (const float*)d_in[8];

    cudaFuncSetAttribute(gemm_norm, cudaFuncAttributeMaxDynamicSharedMemorySize, SMEM_BYTES);

    cudaStream_t s2;
    cudaStreamCreateWithFlags(&s2, cudaStreamNonBlocking);
    cudaEvent_t ef, ej;
    cudaEventCreateWithFlags(&ef, cudaEventDisableTiming);
    cudaEventCreateWithFlags(&ej, cudaEventDisableTiming);

    prep_kernel<<<Bb, 256>>>(ids, offs);
    cudaEventRecord(ef, 0);
    cudaStreamWaitEvent(s2, ef, 0);

    // side chain (stream s2): exact dot path
    xproj_kernel<<<dim3(8, Bb), 128, 0, s2>>>(q, Wm, bias);
    zcomp_kernel<<<dim3(8, ZP), 128, 0, s2>>>(Wm);
    zred_kernel<<<Bb, 256, 0, s2>>>(bias);
    dotk_kernel<<<Mm, 128, 0, s2>>>(seq);
    cudaEventRecord(ej, s2);

    // main chain: 1-pass norm GEMM
    gemm_norm<<<dim3(NBLK, Mm / GM), 256, SMEM_BYTES>>>(seq, Wm, bias);

    cudaStreamWaitEvent(0, ej, 0);
    combine_kernel<<<1, 1024>>>(labels, events, (float*)d_out);
}

// round 8
// speedup vs baseline: 6.2325x; 1.1332x over previous
#include <cuda_runtime.h>
#include <cuda_bf16.h>
#include <cstdint>

#define MASK_ID 50264
#define Bb 16
#define Ss 2048
#define Hh 1024
#define Ll 128
#define Mm (Bb*Ll)      // 2048
#define NBLK 8          // GEMM column blocks
#define XPB 128         // xproj blocks
#define ZCB 32          // zcomp blocks

// ---------------- device scratch ----------------
__device__ int   g_maskpos[Bb];
__device__ int   g_off[Ll];
__device__ float g_x[Bb*Hh];
__device__ float g_z[Bb*Hh];
__device__ float g_xnp[XPB][Bb];
__device__ float g_xbp[XPB][Bb];
__device__ float g_dot[Mm];
__device__ float g_nnp[NBLK][Mm];

// ---------------- kernel 1: prep (17 blocks): offsets + per-batch mask scan ----------------
__global__ void prep_kernel(const int* __restrict__ ids_w, const int* __restrict__ off_w) {
    __shared__ int s_flag;
    __shared__ int s_min[256];
    int blk = blockIdx.x, t = threadIdx.x;
    if (t == 0) s_flag = 0;
    __syncthreads();
    int nz = 0;
    for (int i = t; i < 2048; i += 256) nz |= ids_w[2 * i + 1];
    if (nz) atomicOr(&s_flag, 1);
    __syncthreads();
    const bool is64 = (s_flag == 0);
    if (blk == Bb) {
        if (t < Ll) g_off[t] = is64 ? (int)((const long long*)off_w)[t] : off_w[t];
        return;
    }
    int b = blk;
    const long long* ids64 = (const long long*)ids_w;
    int mi = 0x7fffffff;
    for (int s = t; s < Ss; s += 256) {
        long long v = is64 ? ids64[(size_t)b * Ss + s] : (long long)ids_w[b * Ss + s];
        if (v == MASK_ID && s < mi) mi = s;
    }
    s_min[t] = mi;
    __syncthreads();
    for (int w = 128; w > 0; w >>= 1) {
        if (t < w) s_min[t] = min(s_min[t], s_min[t + w]);
        __syncthreads();
    }
    if (t == 0) g_maskpos[b] = (s_min[0] == 0x7fffffff) ? 0 : s_min[0];
}

// ---------------- kernel 2: x projection, W read once (grid 128, 256 thr) ----------------
// block oc owns 8 output rows o = oc*8 + wid, for ALL 16 batches.
__global__ void xproj_kernel(const float* __restrict__ q, const float* __restrict__ Wm,
                             const float* __restrict__ bias) {
    extern __shared__ __align__(16) float sq[];      // [16][1024] = 64 KB
    __shared__ float sxn[8][Bb], sxb[8][Bb];
    int oc = blockIdx.x, t = threadIdx.x, wid = t >> 5, lane = t & 31;
    // gather 16 masked q rows
    #pragma unroll
    for (int i = 0; i < 16; i++) {
        int idx = t + i * 256;               // 4096 float4
        int b = idx >> 8, h4 = idx & 255;
        ((float4*)sq)[idx] = *(const float4*)(q + ((size_t)b * Ss + g_maskpos[b]) * Hh + h4 * 4);
    }
    __syncthreads();
    int o = oc * 8 + wid;
    const float* wr = Wm + (size_t)o * Hh;
    float acc[Bb];
    #pragma unroll
    for (int b = 0; b < Bb; b++) acc[b] = 0.f;
    #pragma unroll
    for (int j = 0; j < 8; j++) {
        int h0 = j * 128 + lane * 4;
        float4 w4 = *(const float4*)(wr + h0);
        #pragma unroll
        for (int b = 0; b < Bb; b++) {
            float4 qv = *(const float4*)(sq + b * Hh + h0);
            acc[b] += w4.x * qv.x + w4.y * qv.y + w4.z * qv.z + w4.w * qv.w;
        }
    }
    #pragma unroll
    for (int b = 0; b < Bb; b++)
        #pragma unroll
        for (int d = 16; d > 0; d >>= 1)
            acc[b] += __shfl_xor_sync(0xffffffffu, acc[b], d);
    if (lane == 0) {
        float bo = bias[o];
        #pragma unroll
        for (int b = 0; b < Bb; b++) {
            float v = acc[b] + bo;
            g_x[b * Hh + o] = v;
            sxn[wid][b] = v * v;
            sxb[wid][b] = v * bo;
        }
    }
    __syncthreads();
    if (t < Bb) {
        float xn = 0.f, xb = 0.f;
        #pragma unroll
        for (int w = 0; w < 8; w++) { xn += sxn[w][t]; xb += sxb[w][t]; }
        g_xnp[oc][t] = xn;
        g_xbp[oc][t] = xb;
    }
}

// ---------------- kernel 3: z = W^T x, W read once (grid 32, 256 thr) ----------------
// block owns 32 h-columns for ALL batches; threads: hlane = t&31, ochunk = t>>5 (8 x 128 o)
__global__ void zcomp_kernel(const float* __restrict__ Wm) {
    extern __shared__ __align__(16) float sx[];      // [16][1024] = 64 KB
    __shared__ float spz[8][Bb][32];                 // 16 KB partials
    int t = threadIdx.x, hlane = t & 31, och = t >> 5;
    int h = blockIdx.x * 32 + hlane;
    #pragma unroll
    for (int i = 0; i < 16; i++) {
        int idx = t + i * 256;
        ((float4*)sx)[idx] = ((const float4*)g_x)[idx];
    }
    __syncthreads();
    float acc[Bb];
    #pragma unroll
    for (int b = 0; b < Bb; b++) acc[b] = 0.f;
    #pragma unroll 4
    for (int o = och * 128; o < och * 128 + 128; o++) {
        float w = Wm[(size_t)o * Hh + h];
        #pragma unroll
        for (int b = 0; b < Bb; b++) acc[b] += sx[b * Hh + o] * w;
    }
    #pragma unroll
    for (int b = 0; b < Bb; b++) spz[och][b][hlane] = acc[b];
    __syncthreads();
    // reduce 8 chunks: 512 outputs / 256 threads = 2 each
    #pragma unroll
    for (int r = 0; r < 2; r++) {
        int idx = t + r * 256;             // (b, hlane)
        int b = idx >> 5, hl = idx & 31;
        float z = 0.f;
        #pragma unroll
        for (int c = 0; c < 8; c++) z += spz[c][b][hl];
        g_z[b * Hh + blockIdx.x * 32 + hl] = z;
    }
}

// ---------------- kernel 4: per-row exact dot = a . z ----------------
__global__ void dotk_kernel(const float* __restrict__ seq) {
    __shared__ float sred[4];
    int r = blockIdx.x, t = threadIdx.x;   // 128 threads
    int b = r >> 7, l = r & 127;
    const float4* a4 = (const float4*)(seq + ((size_t)b * Ss + g_off[l]) * Hh);
    const float4* z4 = (const float4*)(g_z + b * Hh);
    float d = 0.f;
    #pragma unroll
    for (int i = t; i < Hh / 4; i += 128) {
        float4 av = a4[i], zv = z4[i];
        d += av.x * zv.x + av.y * zv.y + av.z * zv.z + av.w * zv.w;
    }
    #pragma unroll
    for (int s = 16; s > 0; s >>= 1) d += __shfl_xor_sync(0xffffffffu, d, s);
    int w = t >> 5;
    if ((t & 31) == 0) sred[w] = d;
    __syncthreads();
    if (t == 0) g_dot[r] = sred[0] + sred[1] + sred[2] + sred[3];
}

// ---------------- kernel 5: 1-pass bf16 HMMA GEMM for ||y||^2 partials ----------------
#define GM 128
#define GN 128
#define GK 32
#define NC (Hh / GK)
#define SP 40
#define AHI 0
#define BHI (128*SP)
#define BUFS (2*128*SP)
#define SMEM_BYTES (2*BUFS*2)   // 40960 B

__device__ __forceinline__ void mma16816(float* d, const uint32_t* a, const uint32_t* b) {
    asm volatile("mma.sync.aligned.m16n8k16.row.col.f32.bf16.bf16.f32 "
                 "{%0,%1,%2,%3},{%4,%5,%6,%7},{%8,%9},{%0,%1,%2,%3};"
                 : "+f"(d[0]), "+f"(d[1]), "+f"(d[2]), "+f"(d[3])
                 : "r"(a[0]), "r"(a[1]), "r"(a[2]), "r"(a[3]), "r"(b[0]), "r"(b[1]));
}
__device__ __forceinline__ uint32_t lds_u32(const __nv_bfloat16* p) {
    return *(const uint32_t*)p;
}
__device__ __forceinline__ void conv_hi(__nv_bfloat16* hi, const float4& v) {
    const float* f = (const float*)&v;
    *(__nv_bfloat162*)(hi)     = __float22bfloat162_rn(make_float2(f[0], f[1]));
    *(__nv_bfloat162*)(hi + 2) = __float22bfloat162_rn(make_float2(f[2], f[3]));
}

__global__ __launch_bounds__(256, 1) void gemm_norm(const float* __restrict__ seq,
                                                    const float* __restrict__ Wm,
                                                    const float* __restrict__ bias) {
    extern __shared__ __align__(16) __nv_bfloat16 sm[];
    __shared__ float snn[4][GM];
    int t = threadIdx.x, wid = t >> 5, lane = t & 31;
    int wm = wid >> 2, wn = wid & 3;
    int m0 = blockIdx.y * GM, n0 = blockIdx.x * GN;
    int g = lane >> 2, tq = lane & 3;

    const float* aptr[4];
    const float* bptr[4];
    int arow_[4], aq_[4];
    #pragma unroll
    for (int p = 0; p < 4; p++) {
        int j = t + p * 256;
        int row = j >> 3, qq = j & 7;
        arow_[p] = row; aq_[p] = qq;
        int r = m0 + row;
        aptr[p] = seq + ((size_t)(r >> 7) * Ss + g_off[r & 127]) * Hh + qq * 4;
        bptr[p] = Wm + (size_t)(n0 + row) * Hh + qq * 4;
    }

    float acc[4][4][4];
    #pragma unroll
    for (int mt = 0; mt < 4; mt++)
        #pragma unroll
        for (int nt = 0; nt < 4; nt++)
            #pragma unroll
            for (int e = 0; e < 4; e++) acc[mt][nt][e] = 0.f;

    float4 av[4], bv[4];
    #pragma unroll
    for (int p = 0; p < 4; p++) { av[p] = *(const float4*)aptr[p]; bv[p] = *(const float4*)bptr[p]; }
    {
        __nv_bfloat16* sb = sm;
        #pragma unroll
        for (int p = 0; p < 4; p++) {
            int off = arow_[p] * SP + aq_[p] * 4;
            conv_hi(sb + AHI + off, av[p]);
            conv_hi(sb + BHI + off, bv[p]);
        }
    }
    __syncthreads();

    for (int c = 0; c < NC; c++) {
        if (c + 1 < NC) {
            #pragma unroll
            for (int p = 0; p < 4; p++) {
                av[p] = *(const float4*)(aptr[p] + (c + 1) * GK);
                bv[p] = *(const float4*)(bptr[p] + (c + 1) * GK);
            }
        }
        const __nv_bfloat16* sb = sm + (c & 1) * BUFS;
        #pragma unroll
        for (int ks = 0; ks < 2; ks++) {
            int kb = ks * 16 + tq * 2;
            uint32_t bh[4][2];
            #pragma unroll
            for (int nt = 0; nt < 4; nt++) {
                int nrow = wn * 32 + nt * 8 + g;
                bh[nt][0] = lds_u32(sb + BHI + nrow * SP + kb);
                bh[nt][1] = lds_u32(sb + BHI + nrow * SP + kb + 8);
            }
            #pragma unroll
            for (int mt = 0; mt < 4; mt++) {
                int mrow = wm * 64 + mt * 16 + g;
                uint32_t ah[4];
                ah[0] = lds_u32(sb + AHI + mrow * SP + kb);
                ah[1] = lds_u32(sb + AHI + (mrow + 8) * SP + kb);
                ah[2] = lds_u32(sb + AHI + mrow * SP + kb + 8);
                ah[3] = lds_u32(sb + AHI + (mrow + 8) * SP + kb + 8);
                #pragma unroll
                for (int nt = 0; nt < 4; nt++) mma16816(acc[mt][nt], ah, bh[nt]);
            }
        }
        if (c + 1 < NC) {
            __nv_bfloat16* sw = sm + ((c + 1) & 1) * BUFS;
            #pragma unroll
            for (int p = 0; p < 4; p++) {
                int off = arow_[p] * SP + aq_[p] * 4;
                conv_hi(sw + AHI + off, av[p]);
                conv_hi(sw + BHI + off, bv[p]);
            }
        }
        __syncthreads();
    }

    // epilogue: per-row ||y||^2 partials (y = acc + bias)
    float bb[4][2];
    #pragma unroll
    for (int nt = 0; nt < 4; nt++) {
        int gc = n0 + wn * 32 + nt * 8 + tq * 2;
        bb[nt][0] = bias[gc];
        bb[nt][1] = bias[gc + 1];
    }
    #pragma unroll
    for (int mt = 0; mt < 4; mt++) {
        #pragma unroll
        for (int h = 0; h < 2; h++) {
            float nr = 0.f;
            #pragma unroll
            for (int nt = 0; nt < 4; nt++) {
                float y0 = acc[mt][nt][2 * h]     + bb[nt][0];
                float y1 = acc[mt][nt][2 * h + 1] + bb[nt][1];
                nr += y0 * y0 + y1 * y1;
            }
            nr += __shfl_xor_sync(0xffffffffu, nr, 1);
            nr += __shfl_xor_sync(0xffffffffu, nr, 2);
            if (tq == 0) snn[wn][wm * 64 + mt * 16 + h * 8 + g] = nr;
        }
    }
    __syncthreads();
    if (t < GM)
        g_nnp[blockIdx.x][m0 + t] = snn[0][t] + snn[1][t] + snn[2][t] + snn[3][t];
}

// ---------------- kernel 6: combine + final loss (one block) ----------------
__global__ void combine_kernel(const int* __restrict__ labels, const int* __restrict__ events,
                               float* __restrict__ out) {
    __shared__ float s_num[64], s_den[64];
    __shared__ float s_xn[Bb], s_xb[Bb];
    int t = threadIdx.x;   // 1024 threads
    int w = t >> 5, lane = t & 31;
    if (t < Bb) {
        float X = 0.f, XB = 0.f;
        for (int p = 0; p < XPB; p++) { X += g_xnp[p][t]; XB += g_xbp[p][t]; }
        s_xn[t] = sqrtf(X);
        s_xb[t] = XB;
    }
    __syncthreads();
    float nums[2], dens[2];
    #pragma unroll
    for (int half = 0; half < 2; half++) {
        int r = t + half * 1024;
        int b = r >> 7;
        float nn = 0.f;
        #pragma unroll
        for (int p = 0; p < NBLK; p++) nn += g_nnp[p][r];
        float e = expf((g_dot[r] + s_xb[b]) / fmaxf(s_xn[b] * sqrtf(nn), 1e-8f));
        nums[half] = e * (float)labels[r];
        dens[half] = e * (float)events[r];
    }
    #pragma unroll
    for (int d = 16; d > 0; d >>= 1) {
        nums[0] += __shfl_xor_sync(0xffffffffu, nums[0], d);
        nums[1] += __shfl_xor_sync(0xffffffffu, nums[1], d);
        dens[0] += __shfl_xor_sync(0xffffffffu, dens[0], d);
        dens[1] += __shfl_xor_sync(0xffffffffu, dens[1], d);
    }
    if (lane == 0) {
        s_num[w]      = nums[0];  s_den[w]      = dens[0];
        s_num[32 + w] = nums[1];  s_den[32 + w] = dens[1];
    }
    __syncthreads();
    if (t < 32) {
        float loss = 0.f;
        if (t < 16) {
            int base = (t < 8) ? 4 * t : 32 + 4 * (t - 8);
            float num = s_num[base] + s_num[base + 1] + s_num[base + 2] + s_num[base + 3];
            float den = s_den[base] + s_den[base + 1] + s_den[base + 2] + s_den[base + 3];
            loss = logf(den) - logf(num);
        }
        #pragma unroll
        for (int d = 16; d > 0; d >>= 1) loss += __shfl_xor_sync(0xffffffffu, loss, d);
        if (t == 0) out[0] = loss / (float)Bb;
    }
}

// ---------------- launcher ----------------
extern "C" void kernel_launch(void* const* d_in, const int* in_sizes, int n_in,
                              void* d_out, int out_size) {
    const int*   ids    = (const int*)d_in[0];
    const float* q      = (const float*)d_in[1];
    const float* seq    = (const float*)d_in[2];
    const int*   events = (const int*)d_in[3];
    const int*   labels = (const int*)d_in[4];
    const int*   offs   = (const int*)d_in[5];
    const float* Wm     = (const float*)d_in[7];
    const float* bias   = (const float*)d_in[8];

    cudaFuncSetAttribute(gemm_norm, cudaFuncAttributeMaxDynamicSharedMemorySize, SMEM_BYTES);
    cudaFuncSetAttribute(xproj_kernel, cudaFuncAttributeMaxDynamicSharedMemorySize, 65536);
    cudaFuncSetAttribute(zcomp_kernel, cudaFuncAttributeMaxDynamicSharedMemorySize, 65536);

    cudaStream_t s2;
    cudaStreamCreateWithFlags(&s2, cudaStreamNonBlocking);
    cudaEvent_t ef, ej;
    cudaEventCreateWithFlags(&ef, cudaEventDisableTiming);
    cudaEventCreateWithFlags(&ej, cudaEventDisableTiming);

    prep_kernel<<<Bb + 1, 256>>>(ids, offs);
    cudaEventRecord(ef, 0);
    cudaStreamWaitEvent(s2, ef, 0);

    // side chain (s2): exact dot path, hides under the GEMM
    xproj_kernel<<<XPB, 256, 65536, s2>>>(q, Wm, bias);
    zcomp_kernel<<<ZCB, 256, 65536, s2>>>(Wm);
    dotk_kernel<<<Mm, 128, 0, s2>>>(seq);
    cudaEventRecord(ej, s2);

    // main chain: 1-pass norm GEMM
    gemm_norm<<<dim3(NBLK, Mm / GM), 256, SMEM_BYTES>>>(seq, Wm, bias);

    cudaStreamWaitEvent(0, ej, 0);
    combine_kernel<<<1, 1024>>>(labels, events, (float*)d_out);
}